// round 15
// baseline (speedup 1.0000x reference)
#include <cuda_runtime.h>
#include <cuda_bf16.h>
#include <cstdint>

// TSM: x (B=4, T=16, H=64, W=64, C=256) fp32
// out[..., 0:64)    = x[t+1, ..., 0:64)   (0 at t=T-1)
// out[..., 64:128)  = x[t-1, ..., 64:128) (0 at t=0)
// out[..., 128:256) = x[t, ..., 128:256)
//
// FINAL — measured optimum (R11/R13/R14: 72.54-73.41us kernel, run-to-run
// noise ±0.9us; DRAM 81-82.3%, 6.45-6.52 TB/s; bench 80.35-80.64us).
// Block-strided unroll x8, .cs load/store, TPB=512, exact-fit 4096-block grid.
//
// Search summary (R1-R14): nine configurations across every axis —
// access width (128/256-bit), unroll (4/8), work mapping (per-thread
// contiguous / block-strided / warp-uniform-dt), grid shape (exact-fit /
// persistent), cache policy (default / .cs / L2::256B), TPB (256/512/1024) —
// all pin at 6.33-6.52 TB/s == the B300 LTS chip-throughput cap (~6300 B/cyc,
// path-independent, LDG ≡ TMA: a TMA pipeline shares the same cap). SM pipes
// <9% utilized throughout; occupancy sweeps 38-89% never bound. Traffic is
// minimal: each output byte written once, each needed input byte read once,
// boundary reads skipped, zero reuse exists in the dataflow. Every variant
// the HW model predicted negative measured negative (persistent -8%,
// v8 -1.5%, L2::256B -1.3%, TPB=1024 -2%).
//
// float4 units: c4 = i & 63; t = (i >> 18) & 15; slab stride = 1<<18 float4.
// dt = +1 (c4<16), -1 (c4<32), 0 otherwise. Invalid src -> 0.
// Every LDG.128/STG.128 perfectly coalesced (consecutive lanes ->
// consecutive float4); 8 independent loads in flight per thread before the
// store batch; .cs hints keep the 512MiB single-touch stream out of L2.

static constexpr int BTSTRIDE = 1 << 18;      // float4 per (b,t) slab
static constexpr long long N4 = 16777216LL;   // total float4
static constexpr int UNROLL = 8;
static constexpr int TPB = 512;
static constexpr int F4_PER_BLOCK = TPB * UNROLL; // 4096

__global__ __launch_bounds__(TPB) void tsm_kernel(const float4* __restrict__ in,
                                                  float4* __restrict__ out)
{
    long long blockBase = (long long)(blockIdx.x) * F4_PER_BLOCK;
    int tid = threadIdx.x;

    float4 v[UNROLL];

    #pragma unroll
    for (int u = 0; u < UNROLL; ++u) {
        long long i = blockBase + u * TPB + tid;
        int c4 = (int)(i & 63);
        int t  = (int)((i >> 18) & 15);

        int dt = (c4 < 16) ? 1 : ((c4 < 32) ? -1 : 0);
        int ts = t + dt;
        bool valid = (unsigned)ts < 16u;

        v[u] = make_float4(0.f, 0.f, 0.f, 0.f);
        if (valid) {
            v[u] = __ldcs(&in[i + (long long)dt * BTSTRIDE]);
        }
    }

    #pragma unroll
    for (int u = 0; u < UNROLL; ++u) {
        long long i = blockBase + u * TPB + tid;
        __stcs(&out[i], v[u]);
    }
}

extern "C" void kernel_launch(void* const* d_in, const int* in_sizes, int n_in,
                              void* d_out, int out_size)
{
    const float4* in = (const float4*)d_in[0];
    float4* out = (float4*)d_out;

    int blocks = (int)(N4 / F4_PER_BLOCK); // 4096
    tsm_kernel<<<blocks, TPB>>>(in, out);
}

// round 16
// speedup vs baseline: 1.0080x; 1.0080x over previous
#include <cuda_runtime.h>
#include <cuda_bf16.h>
#include <cstdint>

// TSM: x (B=4, T=16, H=64, W=64, C=256) fp32
// out[..., 0:64)    = x[t+1, ..., 0:64)   (0 at t=T-1)
// out[..., 64:128)  = x[t-1, ..., 64:128) (0 at t=0)
// out[..., 128:256) = x[t, ..., 128:256)
//
// FINAL — measured optimum (R11/R13/R14/R15: 72.54-73.73us kernel, run-to-run
// noise ±0.9us; DRAM 81-82.3%, 6.42-6.52 TB/s; bench 80.35-80.64us).
// Block-strided unroll x8, .cs load/store, TPB=512, exact-fit 4096-block grid.
//
// Search summary (R1-R15): nine configurations across every axis —
// access width (128/256-bit), unroll (4/8), work mapping (per-thread
// contiguous / block-strided / warp-uniform-dt), grid shape (exact-fit /
// persistent), cache policy (default / .cs / L2::256B), TPB (256/512/1024) —
// all pin at 6.33-6.52 TB/s == the B300 LTS chip-throughput cap (~6300 B/cyc,
// path-independent, LDG ≡ TMA: a TMA pipeline shares the same cap). SM pipes
// <9% utilized throughout; occupancy sweeps 38-89% never bound. Traffic is
// minimal: each output byte written once, each needed input byte read once,
// boundary reads skipped, zero reuse exists in the dataflow. Every variant
// the HW model predicted negative measured negative (persistent -8%,
// v8 -1.5%, L2::256B -1.3%, TPB=1024 -2%); both predicted-positive changes
// (R2 coalescing +13%, R11 TPB=512 +1%) measured positive.
//
// float4 units: c4 = i & 63; t = (i >> 18) & 15; slab stride = 1<<18 float4.
// dt = +1 (c4<16), -1 (c4<32), 0 otherwise. Invalid src -> 0.
// Every LDG.128/STG.128 perfectly coalesced (consecutive lanes ->
// consecutive float4); 8 independent loads in flight per thread before the
// store batch; .cs hints keep the 512MiB single-touch stream out of L2.

static constexpr int BTSTRIDE = 1 << 18;      // float4 per (b,t) slab
static constexpr long long N4 = 16777216LL;   // total float4
static constexpr int UNROLL = 8;
static constexpr int TPB = 512;
static constexpr int F4_PER_BLOCK = TPB * UNROLL; // 4096

__global__ __launch_bounds__(TPB) void tsm_kernel(const float4* __restrict__ in,
                                                  float4* __restrict__ out)
{
    long long blockBase = (long long)(blockIdx.x) * F4_PER_BLOCK;
    int tid = threadIdx.x;

    float4 v[UNROLL];

    #pragma unroll
    for (int u = 0; u < UNROLL; ++u) {
        long long i = blockBase + u * TPB + tid;
        int c4 = (int)(i & 63);
        int t  = (int)((i >> 18) & 15);

        int dt = (c4 < 16) ? 1 : ((c4 < 32) ? -1 : 0);
        int ts = t + dt;
        bool valid = (unsigned)ts < 16u;

        v[u] = make_float4(0.f, 0.f, 0.f, 0.f);
        if (valid) {
            v[u] = __ldcs(&in[i + (long long)dt * BTSTRIDE]);
        }
    }

    #pragma unroll
    for (int u = 0; u < UNROLL; ++u) {
        long long i = blockBase + u * TPB + tid;
        __stcs(&out[i], v[u]);
    }
}

extern "C" void kernel_launch(void* const* d_in, const int* in_sizes, int n_in,
                              void* d_out, int out_size)
{
    const float4* in = (const float4*)d_in[0];
    float4* out = (float4*)d_out;

    int blocks = (int)(N4 / F4_PER_BLOCK); // 4096
    tsm_kernel<<<blocks, TPB>>>(in, out);
}